// round 16
// baseline (speedup 1.0000x reference)
#include <cuda_runtime.h>
#include <cuda_bf16.h>
#include <cuda_fp16.h>
#include <cstdint>

#define NN   100000
#define NE   3200000
#define FIN  1024
#define HID  16
#define NCLS 40

// ---------------- device scratch ----------------
__device__ int    g_deg[NN];
__device__ __align__(16) __half g_Yh[NN * 32];     // per-node interleaved [y0_c, y1_c] x16 (fp16)
__device__ __align__(16) float g_R[NN * 16];       // x@root1
__device__ __align__(16) float g_S1[NN * 16];      // layer-1 message sums
__device__ __align__(16) __nv_bfloat16 g_Wbhi[48 * FIN];  // [n][k] hi split
__device__ __align__(16) __nv_bfloat16 g_Wblo[48 * FIN];  // [n][k] lo split
__device__ __align__(16) __nv_bfloat16 g_W2Thi[48 * 56];  // layer2 W^T [n(pad48)][k48], hi
__device__ __align__(16) __nv_bfloat16 g_W2Tlo[48 * 56];  // lo
__device__ __align__(16) float g_AB[NN * 32];      // per node, channel-interleaved [A_c, B_c] x16
__device__ __align__(16) float g_x1[NN * HID];     // fp32 (for k_out + output)
__device__ __align__(16) __half g_x1h[NN * HID];   // fp16 copy (for edge2 gather)

__device__ __forceinline__ int clampN(int v) {
    v = v < 0 ? 0 : v;
    return v >= NN ? NN - 1 : v;
}

__device__ __forceinline__ uint32_t smem_u32(const void* p) {
    uint32_t a;
    asm("{ .reg .u64 t; cvta.to.shared.u64 t, %1; cvt.u32.u64 %0, t; }" : "=r"(a) : "l"(p));
    return a;
}

// ---------------- zero (S1 + deg) ----------------
__global__ void k_zero() {
    int t = blockIdx.x * blockDim.x + threadIdx.x;
    if (t < NN * 4) ((float4*)g_S1)[t] = make_float4(0.f, 0.f, 0.f, 0.f);
    if (t < NN) g_deg[t] = 0;
}

// ---------------- weight packing ----------------
__global__ void k_packW(const float* __restrict__ W1, const float* __restrict__ root1) {
    int idx = blockIdx.x * blockDim.x + threadIdx.x;
    if (idx >= 48 * FIN) return;
    int n = idx >> 10, k = idx & 1023;
    float v;
    if (n < 16)      v = W1[k * 16 + n];
    else if (n < 32) v = W1[FIN * 16 + k * 16 + (n - 16)];
    else             v = root1[k * 16 + (n - 32)];
    __nv_bfloat16 h = __float2bfloat16(v);
    __nv_bfloat16 l = __float2bfloat16(v - __bfloat162float(h));
    g_Wbhi[idx] = h;
    g_Wblo[idx] = l;
}

// layer-2 weights transposed: W2T[n][k], n padded to 48, k = [W2_0(16) | W2_1(16) | root2(16)]
__global__ void k_pack2(const float* __restrict__ W2, const float* __restrict__ root2) {
    int idx = blockIdx.x * blockDim.x + threadIdx.x;
    if (idx >= 48 * 48) return;
    int n = idx / 48, k = idx % 48;
    float v = 0.f;
    if (n < NCLS) {
        if (k < 16)      v = W2[k * NCLS + n];
        else if (k < 32) v = W2[16 * NCLS + (k - 16) * NCLS + n];
        else             v = root2[(k - 32) * NCLS + n];
    }
    __nv_bfloat16 h = __float2bfloat16(v);
    __nv_bfloat16 l = __float2bfloat16(v - __bfloat162float(h));
    g_W2Thi[n * 56 + k] = h;
    g_W2Tlo[n * 56 + k] = l;
}

// ---------------- GEMM1: cp.async staged A (fp32), 3-stage pipeline ----------------
#define A_STRIDE 40
#define A_SZ     (128 * A_STRIDE * 4)
#define B_STRIDE 40
#define B_SZ     (48 * B_STRIDE * 2)
#define STAGE_SZ (A_SZ + 2 * B_SZ)
#define G1_SMEM  (3 * STAGE_SZ)

#define MMA_BF16(d, a0, a1, a2, a3, b0, b1) \
    asm volatile("mma.sync.aligned.m16n8k16.row.col.f32.bf16.bf16.f32 " \
        "{%0,%1,%2,%3}, {%4,%5,%6,%7}, {%8,%9}, {%0,%1,%2,%3};" \
        : "+f"((d)[0]), "+f"((d)[1]), "+f"((d)[2]), "+f"((d)[3]) \
        : "r"(a0), "r"(a1), "r"(a2), "r"(a3), "r"(b0), "r"(b1))

#define LDSM_X4(r0, r1, r2, r3, addr) \
    asm volatile("ldmatrix.sync.aligned.m8n8.x4.shared.b16 {%0,%1,%2,%3}, [%4];" \
        : "=r"(r0), "=r"(r1), "=r"(r2), "=r"(r3) : "r"(addr))

#define CP_ASYNC16(saddr, gptr) \
    asm volatile("cp.async.cg.shared.global [%0], [%1], 16;" :: "r"(saddr), "l"(gptr))
#define CP_COMMIT() asm volatile("cp.async.commit_group;" ::: "memory")
#define CP_WAIT(n)  asm volatile("cp.async.wait_group %0;" :: "n"(n) : "memory")

__device__ __forceinline__ uint32_t split_hi(float a, float b, uint32_t& lo) {
    __nv_bfloat162 h = __floats2bfloat162_rn(a, b);
    float ra = a - __low2float(h);
    float rb = b - __high2float(h);
    __nv_bfloat162 L = __floats2bfloat162_rn(ra, rb);
    lo = *(uint32_t*)&L;
    return *(uint32_t*)&h;
}

__device__ __forceinline__ void storeC(long row, int j, float v) {
    if (row >= NN) return;
    if (j < 16)      g_Yh[row * 32 + 2 * j] = __float2half_rn(v);
    else if (j < 32) g_Yh[row * 32 + 2 * (j - 16) + 1] = __float2half_rn(v);
    else             g_R[row * 16 + (j - 32)] = v;
}

__device__ __forceinline__ void g1_prefetch(const float* __restrict__ x, long mBase,
                                            int tid, int k0, uint32_t stage) {
    uint32_t sA  = stage;
    uint32_t sBh = stage + A_SZ;
    uint32_t sBl = stage + A_SZ + B_SZ;
#pragma unroll
    for (int i = 0; i < 4; i++) {
        int idx = tid + i * 256;
        int r = idx >> 3, c4 = (idx & 7) * 4;
        long gr = mBase + r;
        if (gr >= NN) gr = NN - 1;
        CP_ASYNC16(sA + (r * A_STRIDE + c4) * 4, x + gr * FIN + k0 + c4);
    }
    if (tid < 192) {
        int n = tid >> 2, c = (tid & 3) * 8;
        CP_ASYNC16(sBh + (n * B_STRIDE + c) * 2, g_Wbhi + n * FIN + k0 + c);
        CP_ASYNC16(sBl + (n * B_STRIDE + c) * 2, g_Wblo + n * FIN + k0 + c);
    }
}

__global__ __launch_bounds__(256, 2) void k_gemm1_mma(const float* __restrict__ x) {
    extern __shared__ __align__(16) char sm[];
    int tid = threadIdx.x, w = tid >> 5, l = tid & 31;
    int lq = l >> 2, lr = l & 3;
    long mBase = (long)blockIdx.x * 128;
    uint32_t smb = smem_u32(sm);

    uint32_t aw = (w * 16 + lq) * A_STRIDE + 2 * lr;
    int n_off = (l & 7) + ((l & 16) ? 8 : 0);
    int kB_off = (l & 8) ? 8 : 0;
    uint32_t bo0 = ((0 * 16 + n_off) * B_STRIDE + kB_off) * 2;
    uint32_t bo1 = ((1 * 16 + n_off) * B_STRIDE + kB_off) * 2;
    uint32_t bo2 = ((2 * 16 + n_off) * B_STRIDE + kB_off) * 2;

    float acc[6][4];
#pragma unroll
    for (int t = 0; t < 6; t++)
#pragma unroll
        for (int i = 0; i < 4; i++) acc[t][i] = 0.f;

    g1_prefetch(x, mBase, tid, 0, smb);
    CP_COMMIT();
    g1_prefetch(x, mBase, tid, 32, smb + STAGE_SZ);
    CP_COMMIT();

    for (int kb = 0; kb < 32; kb++) {
        if (kb < 31) { CP_WAIT(1); } else { CP_WAIT(0); }
        __syncthreads();
        if (kb < 30) {
            g1_prefetch(x, mBase, tid, (kb + 2) * 32, smb + ((kb + 2) % 3) * STAGE_SZ);
            CP_COMMIT();
        }
        int st = kb % 3;
        uint32_t cur = smb + st * STAGE_SZ;
        const float* As = (const float*)(sm + st * STAGE_SZ);
        uint32_t bhb = cur + A_SZ;
        uint32_t blb = cur + A_SZ + B_SZ;
#pragma unroll
        for (int ks = 0; ks < 2; ks++) {
            int kc = ks * 16;
            float2 v0 = *(const float2*)(As + aw + kc);
            float2 v1 = *(const float2*)(As + aw + 8 * A_STRIDE + kc);
            float2 v2 = *(const float2*)(As + aw + kc + 8);
            float2 v3 = *(const float2*)(As + aw + 8 * A_STRIDE + kc + 8);
            uint32_t al0, al1, al2, al3;
            uint32_t ah0 = split_hi(v0.x, v0.y, al0);
            uint32_t ah1 = split_hi(v1.x, v1.y, al1);
            uint32_t ah2 = split_hi(v2.x, v2.y, al2);
            uint32_t ah3 = split_hi(v3.x, v3.y, al3);
            uint32_t ko = ks * 32;
            uint32_t bofs[3] = {bo0, bo1, bo2};
#pragma unroll
            for (int tp = 0; tp < 3; tp++) {
                uint32_t bh0, bh1, bh2, bh3, bl0, bl1, bl2, bl3;
                LDSM_X4(bh0, bh1, bh2, bh3, bhb + bofs[tp] + ko);
                LDSM_X4(bl0, bl1, bl2, bl3, blb + bofs[tp] + ko);
                MMA_BF16(acc[2 * tp],     ah0, ah1, ah2, ah3, bh0, bh1);
                MMA_BF16(acc[2 * tp],     ah0, ah1, ah2, ah3, bl0, bl1);
                MMA_BF16(acc[2 * tp],     al0, al1, al2, al3, bh0, bh1);
                MMA_BF16(acc[2 * tp + 1], ah0, ah1, ah2, ah3, bh2, bh3);
                MMA_BF16(acc[2 * tp + 1], ah0, ah1, ah2, ah3, bl2, bl3);
                MMA_BF16(acc[2 * tp + 1], al0, al1, al2, al3, bh2, bh3);
            }
        }
    }

    long r0 = mBase + w * 16 + lq;
#pragma unroll
    for (int t = 0; t < 6; t++) {
        int j = t * 8 + lr * 2;
        storeC(r0,     j,     acc[t][0]);
        storeC(r0,     j + 1, acc[t][1]);
        storeC(r0 + 8, j,     acc[t][2]);
        storeC(r0 + 8, j + 1, acc[t][3]);
    }
}

// ---------------- layer-1 edge aggregation: 4 threads/edge, fp16 gather, float4 atomics ----------------
__global__ __launch_bounds__(256) void k_edge1(const int* __restrict__ ei,
                                               const float* __restrict__ pa) {
    int t = blockIdx.x * 256 + threadIdx.x;
    int e = t >> 2;
    if (e >= NE) return;
    int c4 = t & 3;
    int src = clampN(ei[e]);
    int dst = clampN(ei[NE + e]);
    float p = pa[e];
    uint4 raw = *(const uint4*)(g_Yh + src * 32 + 8 * c4);  // 8 halves: (y0,y1) x 4 channels
    const __half2* hp = (const __half2*)&raw;
    float4 m;
    {
        float2 f0 = __half22float2(hp[0]);
        float2 f1 = __half22float2(hp[1]);
        float2 f2 = __half22float2(hp[2]);
        float2 f3 = __half22float2(hp[3]);
        m.x = fmaf(p, f0.y - f0.x, f0.x);
        m.y = fmaf(p, f1.y - f1.x, f1.x);
        m.z = fmaf(p, f2.y - f2.x, f2.x);
        m.w = fmaf(p, f3.y - f3.x, f3.x);
    }
    atomicAdd((float4*)(g_S1 + dst * 16 + 4 * c4), m);
    if (c4 == 0) atomicAdd(&g_deg[dst], 1);
}

// ---------------- node update: x1 = elu(S1/deg + R + b1); zero AB ----------------
__global__ __launch_bounds__(256) void k_node1(const float* __restrict__ b1,
                                               float* __restrict__ x1out, int writeOut) {
    int t = blockIdx.x * 256 + threadIdx.x;
    int node = t >> 4;
    if (node >= NN) return;
    int c = t & 15;
    int deg = g_deg[node];
    float inv = 1.f / (float)(deg > 0 ? deg : 1);
    float v = fmaf(g_S1[node * 16 + c], inv, g_R[node * 16 + c] + b1[c]);
    v = (v > 0.f) ? v : expm1f(v);
    g_x1[node * 16 + c] = v;
    g_x1h[node * 16 + c] = __float2half_rn(v);
    if (writeOut) x1out[node * 16 + c] = v;
    g_AB[node * 32 + 2 * c] = 0.f;
    g_AB[node * 32 + 2 * c + 1] = 0.f;
}

// ---------------- layer-2 edge aggregation: 4 threads/edge, fp16 gather, float4 atomics ----------------
// g_AB layout per node: [A_0,B_0, A_1,B_1, ..., A_15,B_15]
__global__ __launch_bounds__(256) void k_edge2(const int* __restrict__ ei,
                                               const float* __restrict__ pa) {
    int t = blockIdx.x * 256 + threadIdx.x;
    int e = t >> 2;
    if (e >= NE) return;
    int c4 = t & 3;
    int src = clampN(ei[e]);
    int dst = clampN(ei[NE + e]);
    float p = pa[e];
    float q = 1.f - p;
    uint2 raw = *(const uint2*)(g_x1h + src * 16 + 4 * c4);  // 4 halves
    const __half2* hp = (const __half2*)&raw;
    float2 fa = __half22float2(hp[0]);
    float2 fb = __half22float2(hp[1]);
    float4 ab0 = make_float4(q * fa.x, p * fa.x, q * fa.y, p * fa.y);
    float4 ab1 = make_float4(q * fb.x, p * fb.x, q * fb.y, p * fb.y);
    atomicAdd((float4*)(g_AB + dst * 32 + 8 * c4),     ab0);
    atomicAdd((float4*)(g_AB + dst * 32 + 8 * c4 + 4), ab1);
}

// ---------------- GEMM2 + log_softmax via mma: [128x48] @ W2T[48x48pad] per CTA ----------------
#define ZST 52   // Z smem row stride (fp32 words)
__global__ __launch_bounds__(256) void k_out_mma(const float* __restrict__ b2,
                                                 float* __restrict__ out) {
    __shared__ __align__(16) float Zs[128 * ZST];
    __shared__ __align__(16) __nv_bfloat16 Whi[48 * 56];
    __shared__ __align__(16) __nv_bfloat16 Wlo[48 * 56];
    __shared__ float b2s[NCLS];
    int tid = threadIdx.x, w = tid >> 5, l = tid & 31;
    int lq = l >> 2, lr = l & 3;
    long mBase = (long)blockIdx.x * 128;

    // ---- fill Z: 2 threads per node ----
    {
        int node2 = tid >> 1, half = tid & 1;
        long gnode = mBase + node2;
        int cn = (gnode < NN) ? (int)gnode : (NN - 1);
        int deg = g_deg[cn];
        float inv = 1.f / (float)(deg > 0 ? deg : 1);
        const float4* abp = (const float4*)(g_AB + cn * 32 + half * 16);
        float* zr = Zs + node2 * ZST;
        int cb = half * 8;
#pragma unroll
        for (int i = 0; i < 4; i++) {
            float4 u = abp[i];
            zr[cb + 2 * i]          = u.x * inv;
            zr[16 + cb + 2 * i]     = u.y * inv;
            zr[cb + 2 * i + 1]      = u.z * inv;
            zr[16 + cb + 2 * i + 1] = u.w * inv;
        }
        const float4* xp = (const float4*)(g_x1 + cn * 16 + half * 8);
        float4 x0 = xp[0], x1v = xp[1];
        zr[32 + cb + 0] = x0.x; zr[32 + cb + 1] = x0.y;
        zr[32 + cb + 2] = x0.z; zr[32 + cb + 3] = x0.w;
        zr[32 + cb + 4] = x1v.x; zr[32 + cb + 5] = x1v.y;
        zr[32 + cb + 6] = x1v.z; zr[32 + cb + 7] = x1v.w;
    }
    for (int i = tid; i < 48 * 56 / 8; i += 256) {
        ((uint4*)Whi)[i] = ((const uint4*)g_W2Thi)[i];
        ((uint4*)Wlo)[i] = ((const uint4*)g_W2Tlo)[i];
    }
    if (tid < NCLS) b2s[tid] = b2[tid];
    __syncthreads();

    uint32_t whi_b = smem_u32(Whi);
    uint32_t wlo_b = smem_u32(Wlo);
    uint32_t aw = (w * 16 + lq) * ZST + 2 * lr;
    int n_off = (l & 7) + ((l & 16) ? 8 : 0);
    int kB_off = (l & 8) ? 8 : 0;
    uint32_t bo0 = ((0 * 16 + n_off) * 56 + kB_off) * 2;
    uint32_t bo1 = ((1 * 16 + n_off) * 56 + kB_off) * 2;
    uint32_t bo2 = ((2 * 16 + n_off) * 56 + kB_off) * 2;

    float acc[6][4];
#pragma unroll
    for (int t = 0; t < 6; t++)
#pragma unroll
        for (int i = 0; i < 4; i++) acc[t][i] = 0.f;

#pragma unroll
    for (int ks = 0; ks < 3; ks++) {
        int kc = ks * 16;
        float2 v0 = *(const float2*)(Zs + aw + kc);
        float2 v1 = *(const float2*)(Zs + aw + 8 * ZST + kc);
        float2 v2 = *(const float2*)(Zs + aw + kc + 8);
        float2 v3 = *(const float2*)(Zs + aw + 8 * ZST + kc + 8);
        uint32_t al0, al1, al2, al3;
        uint32_t ah0 = split_hi(v0.x, v0.y, al0);
        uint32_t ah1 = split_hi(v1.x, v1.y, al1);
        uint32_t ah2 = split_hi(v2.x, v2.y, al2);
        uint32_t ah3 = split_hi(v3.x, v3.y, al3);
        uint32_t ko = ks * 32;
        uint32_t bofs[3] = {bo0, bo1, bo2};
#pragma unroll
        for (int tp = 0; tp < 3; tp++) {
            uint32_t bh0, bh1, bh2, bh3, bl0, bl1, bl2, bl3;
            LDSM_X4(bh0, bh1, bh2, bh3, whi_b + bofs[tp] + ko);
            LDSM_X4(bl0, bl1, bl2, bl3, wlo_b + bofs[tp] + ko);
            MMA_BF16(acc[2 * tp],     ah0, ah1, ah2, ah3, bh0, bh1);
            MMA_BF16(acc[2 * tp],     ah0, ah1, ah2, ah3, bl0, bl1);
            MMA_BF16(acc[2 * tp],     al0, al1, al2, al3, bh0, bh1);
            MMA_BF16(acc[2 * tp + 1], ah0, ah1, ah2, ah3, bh2, bh3);
            MMA_BF16(acc[2 * tp + 1], ah0, ah1, ah2, ah3, bl2, bl3);
            MMA_BF16(acc[2 * tp + 1], al0, al1, al2, al3, bh2, bh3);
        }
    }

#pragma unroll
    for (int t = 0; t < 5; t++) {
        int j = t * 8 + 2 * lr;
        acc[t][0] += b2s[j];     acc[t][1] += b2s[j + 1];
        acc[t][2] += b2s[j];     acc[t][3] += b2s[j + 1];
    }
    float mA = -1e30f, mB = -1e30f;
#pragma unroll
    for (int t = 0; t < 5; t++) {
        mA = fmaxf(mA, fmaxf(acc[t][0], acc[t][1]));
        mB = fmaxf(mB, fmaxf(acc[t][2], acc[t][3]));
    }
    mA = fmaxf(mA, __shfl_xor_sync(0xffffffffu, mA, 1));
    mA = fmaxf(mA, __shfl_xor_sync(0xffffffffu, mA, 2));
    mB = fmaxf(mB, __shfl_xor_sync(0xffffffffu, mB, 1));
    mB = fmaxf(mB, __shfl_xor_sync(0xffffffffu, mB, 2));
    float sA = 0.f, sB = 0.f;
#pragma unroll
    for (int t = 0; t < 5; t++) {
        sA += expf(acc[t][0] - mA) + expf(acc[t][1] - mA);
        sB += expf(acc[t][2] - mB) + expf(acc[t][3] - mB);
    }
    sA += __shfl_xor_sync(0xffffffffu, sA, 1);
    sA += __shfl_xor_sync(0xffffffffu, sA, 2);
    sB += __shfl_xor_sync(0xffffffffu, sB, 1);
    sB += __shfl_xor_sync(0xffffffffu, sB, 2);
    float lA = mA + logf(sA);
    float lB = mB + logf(sB);

    long rA = mBase + w * 16 + lq;
    long rB = rA + 8;
#pragma unroll
    for (int t = 0; t < 5; t++) {
        int j = t * 8 + 2 * lr;
        if (rA < NN) {
            out[rA * NCLS + j]     = acc[t][0] - lA;
            out[rA * NCLS + j + 1] = acc[t][1] - lA;
        }
        if (rB < NN) {
            out[rB * NCLS + j]     = acc[t][2] - lB;
            out[rB * NCLS + j + 1] = acc[t][3] - lB;
        }
    }
}

// ---------------- launch ----------------
extern "C" void kernel_launch(void* const* d_in, const int* in_sizes, int n_in,
                              void* d_out, int out_size) {
    const float* x     = (const float*)d_in[0];
    const int*   ei    = (const int*)d_in[1];     // int32 (jax x64 disabled)
    const float* pa    = (const float*)d_in[2];
    const float* W1    = (const float*)d_in[3];
    const float* root1 = (const float*)d_in[4];
    const float* b1    = (const float*)d_in[5];
    const float* W2    = (const float*)d_in[6];
    const float* root2 = (const float*)d_in[7];
    const float* b2    = (const float*)d_in[8];
    float* out = (float*)d_out;

    int writeOut = (out_size >= NN * (NCLS + HID)) ? 1 : 0;
    float* x1out = out + (long)NN * NCLS;

    cudaFuncSetAttribute(k_gemm1_mma, cudaFuncAttributeMaxDynamicSharedMemorySize, G1_SMEM);

    // order: k_edge1 in the profiled 4th slot
    k_packW<<<(48 * FIN + 255) / 256, 256>>>(W1, root1);
    k_zero<<<(NN * 4 + 255) / 256, 256>>>();
    k_gemm1_mma<<<(NN + 127) / 128, 256, G1_SMEM>>>(x);
    k_edge1<<<(NE * 4) / 256, 256>>>(ei, pa);
    k_node1<<<(NN * 16 + 255) / 256, 256>>>(b1, x1out, writeOut);
    k_edge2<<<(NE * 4) / 256, 256>>>(ei, pa);
    k_pack2<<<(48 * 48 + 255) / 256, 256>>>(W2, root2);
    k_out_mma<<<(NN + 127) / 128, 256>>>(b2, out);
}

// round 17
// speedup vs baseline: 1.0911x; 1.0911x over previous
#include <cuda_runtime.h>
#include <cuda_bf16.h>
#include <cstdint>

#define NN   100000
#define NE   3200000
#define FIN  1024
#define HID  16
#define NCLS 40

// ---------------- device scratch ----------------
__device__ int    g_deg[NN];
__device__ __align__(16) float g_Y[NN * 32];       // per-node interleaved [y0_c, y1_c] x16
__device__ __align__(16) float g_R[NN * 16];       // x@root1
__device__ __align__(16) float g_S1[NN * 16];      // layer-1 message sums
__device__ __align__(16) __nv_bfloat16 g_Wbhi[48 * FIN];  // [n][k] hi split
__device__ __align__(16) __nv_bfloat16 g_Wblo[48 * FIN];  // [n][k] lo split
__device__ __align__(16) __nv_bfloat16 g_W2Thi[48 * 56];  // layer2 W^T [n(pad48)][k48], hi
__device__ __align__(16) __nv_bfloat16 g_W2Tlo[48 * 56];  // lo
__device__ __align__(16) float g_AB[NN * 32];      // per node, channel-interleaved [A_c, B_c] x16
__device__ __align__(16) float g_x1[NN * HID];

__device__ __forceinline__ int clampN(int v) {
    v = v < 0 ? 0 : v;
    return v >= NN ? NN - 1 : v;
}

__device__ __forceinline__ uint32_t smem_u32(const void* p) {
    uint32_t a;
    asm("{ .reg .u64 t; cvta.to.shared.u64 t, %1; cvt.u32.u64 %0, t; }" : "=r"(a) : "l"(p));
    return a;
}

// ---------------- zero (S1 + deg + AB) ----------------
__global__ void k_zero() {
    int t = blockIdx.x * blockDim.x + threadIdx.x;
    if (t < NN * 4) ((float4*)g_S1)[t] = make_float4(0.f, 0.f, 0.f, 0.f);
    if (t < NN * 8) ((float4*)g_AB)[t] = make_float4(0.f, 0.f, 0.f, 0.f);
    if (t < NN) g_deg[t] = 0;
}

// ---------------- weight packing ----------------
__global__ void k_packW(const float* __restrict__ W1, const float* __restrict__ root1) {
    int idx = blockIdx.x * blockDim.x + threadIdx.x;
    if (idx >= 48 * FIN) return;
    int n = idx >> 10, k = idx & 1023;
    float v;
    if (n < 16)      v = W1[k * 16 + n];
    else if (n < 32) v = W1[FIN * 16 + k * 16 + (n - 16)];
    else             v = root1[k * 16 + (n - 32)];
    __nv_bfloat16 h = __float2bfloat16(v);
    __nv_bfloat16 l = __float2bfloat16(v - __bfloat162float(h));
    g_Wbhi[idx] = h;
    g_Wblo[idx] = l;
}

// layer-2 weights transposed: W2T[n][k], n padded to 48, k = [W2_0(16) | W2_1(16) | root2(16)]
__global__ void k_pack2(const float* __restrict__ W2, const float* __restrict__ root2) {
    int idx = blockIdx.x * blockDim.x + threadIdx.x;
    if (idx >= 48 * 48) return;
    int n = idx / 48, k = idx % 48;
    float v = 0.f;
    if (n < NCLS) {
        if (k < 16)      v = W2[k * NCLS + n];
        else if (k < 32) v = W2[16 * NCLS + (k - 16) * NCLS + n];
        else             v = root2[(k - 32) * NCLS + n];
    }
    __nv_bfloat16 h = __float2bfloat16(v);
    __nv_bfloat16 l = __float2bfloat16(v - __bfloat162float(h));
    g_W2Thi[n * 56 + k] = h;
    g_W2Tlo[n * 56 + k] = l;
}

// ---------------- GEMM1: cp.async staged A (fp32), 3-stage pipeline ----------------
#define A_STRIDE 40
#define A_SZ     (128 * A_STRIDE * 4)
#define B_STRIDE 40
#define B_SZ     (48 * B_STRIDE * 2)
#define STAGE_SZ (A_SZ + 2 * B_SZ)
#define G1_SMEM  (3 * STAGE_SZ)

#define MMA_BF16(d, a0, a1, a2, a3, b0, b1) \
    asm volatile("mma.sync.aligned.m16n8k16.row.col.f32.bf16.bf16.f32 " \
        "{%0,%1,%2,%3}, {%4,%5,%6,%7}, {%8,%9}, {%0,%1,%2,%3};" \
        : "+f"((d)[0]), "+f"((d)[1]), "+f"((d)[2]), "+f"((d)[3]) \
        : "r"(a0), "r"(a1), "r"(a2), "r"(a3), "r"(b0), "r"(b1))

#define LDSM_X4(r0, r1, r2, r3, addr) \
    asm volatile("ldmatrix.sync.aligned.m8n8.x4.shared.b16 {%0,%1,%2,%3}, [%4];" \
        : "=r"(r0), "=r"(r1), "=r"(r2), "=r"(r3) : "r"(addr))

#define CP_ASYNC16(saddr, gptr) \
    asm volatile("cp.async.cg.shared.global [%0], [%1], 16;" :: "r"(saddr), "l"(gptr))
#define CP_COMMIT() asm volatile("cp.async.commit_group;" ::: "memory")
#define CP_WAIT(n)  asm volatile("cp.async.wait_group %0;" :: "n"(n) : "memory")

__device__ __forceinline__ uint32_t split_hi(float a, float b, uint32_t& lo) {
    __nv_bfloat162 h = __floats2bfloat162_rn(a, b);
    float ra = a - __low2float(h);
    float rb = b - __high2float(h);
    __nv_bfloat162 L = __floats2bfloat162_rn(ra, rb);
    lo = *(uint32_t*)&L;
    return *(uint32_t*)&h;
}

__device__ __forceinline__ void storeC(long row, int j, float v) {
    if (row >= NN) return;
    if (j < 16)      g_Y[row * 32 + 2 * j] = v;
    else if (j < 32) g_Y[row * 32 + 2 * (j - 16) + 1] = v;
    else             g_R[row * 16 + (j - 32)] = v;
}

__device__ __forceinline__ void g1_prefetch(const float* __restrict__ x, long mBase,
                                            int tid, int k0, uint32_t stage) {
    uint32_t sA  = stage;
    uint32_t sBh = stage + A_SZ;
    uint32_t sBl = stage + A_SZ + B_SZ;
#pragma unroll
    for (int i = 0; i < 4; i++) {
        int idx = tid + i * 256;
        int r = idx >> 3, c4 = (idx & 7) * 4;
        long gr = mBase + r;
        if (gr >= NN) gr = NN - 1;
        CP_ASYNC16(sA + (r * A_STRIDE + c4) * 4, x + gr * FIN + k0 + c4);
    }
    if (tid < 192) {
        int n = tid >> 2, c = (tid & 3) * 8;
        CP_ASYNC16(sBh + (n * B_STRIDE + c) * 2, g_Wbhi + n * FIN + k0 + c);
        CP_ASYNC16(sBl + (n * B_STRIDE + c) * 2, g_Wblo + n * FIN + k0 + c);
    }
}

__global__ __launch_bounds__(256, 2) void k_gemm1_mma(const float* __restrict__ x) {
    extern __shared__ __align__(16) char sm[];
    int tid = threadIdx.x, w = tid >> 5, l = tid & 31;
    int lq = l >> 2, lr = l & 3;
    long mBase = (long)blockIdx.x * 128;
    uint32_t smb = smem_u32(sm);

    uint32_t aw = (w * 16 + lq) * A_STRIDE + 2 * lr;
    int n_off = (l & 7) + ((l & 16) ? 8 : 0);
    int kB_off = (l & 8) ? 8 : 0;
    uint32_t bo0 = ((0 * 16 + n_off) * B_STRIDE + kB_off) * 2;
    uint32_t bo1 = ((1 * 16 + n_off) * B_STRIDE + kB_off) * 2;
    uint32_t bo2 = ((2 * 16 + n_off) * B_STRIDE + kB_off) * 2;

    float acc[6][4];
#pragma unroll
    for (int t = 0; t < 6; t++)
#pragma unroll
        for (int i = 0; i < 4; i++) acc[t][i] = 0.f;

    g1_prefetch(x, mBase, tid, 0, smb);
    CP_COMMIT();
    g1_prefetch(x, mBase, tid, 32, smb + STAGE_SZ);
    CP_COMMIT();

    for (int kb = 0; kb < 32; kb++) {
        if (kb < 31) { CP_WAIT(1); } else { CP_WAIT(0); }
        __syncthreads();
        if (kb < 30) {
            g1_prefetch(x, mBase, tid, (kb + 2) * 32, smb + ((kb + 2) % 3) * STAGE_SZ);
            CP_COMMIT();
        }
        int st = kb % 3;
        uint32_t cur = smb + st * STAGE_SZ;
        const float* As = (const float*)(sm + st * STAGE_SZ);
        uint32_t bhb = cur + A_SZ;
        uint32_t blb = cur + A_SZ + B_SZ;
#pragma unroll
        for (int ks = 0; ks < 2; ks++) {
            int kc = ks * 16;
            float2 v0 = *(const float2*)(As + aw + kc);
            float2 v1 = *(const float2*)(As + aw + 8 * A_STRIDE + kc);
            float2 v2 = *(const float2*)(As + aw + kc + 8);
            float2 v3 = *(const float2*)(As + aw + 8 * A_STRIDE + kc + 8);
            uint32_t al0, al1, al2, al3;
            uint32_t ah0 = split_hi(v0.x, v0.y, al0);
            uint32_t ah1 = split_hi(v1.x, v1.y, al1);
            uint32_t ah2 = split_hi(v2.x, v2.y, al2);
            uint32_t ah3 = split_hi(v3.x, v3.y, al3);
            uint32_t ko = ks * 32;
            uint32_t bofs[3] = {bo0, bo1, bo2};
#pragma unroll
            for (int tp = 0; tp < 3; tp++) {
                uint32_t bh0, bh1, bh2, bh3, bl0, bl1, bl2, bl3;
                LDSM_X4(bh0, bh1, bh2, bh3, bhb + bofs[tp] + ko);
                LDSM_X4(bl0, bl1, bl2, bl3, blb + bofs[tp] + ko);
                MMA_BF16(acc[2 * tp],     ah0, ah1, ah2, ah3, bh0, bh1);
                MMA_BF16(acc[2 * tp],     ah0, ah1, ah2, ah3, bl0, bl1);
                MMA_BF16(acc[2 * tp],     al0, al1, al2, al3, bh0, bh1);
                MMA_BF16(acc[2 * tp + 1], ah0, ah1, ah2, ah3, bh2, bh3);
                MMA_BF16(acc[2 * tp + 1], ah0, ah1, ah2, ah3, bl2, bl3);
                MMA_BF16(acc[2 * tp + 1], al0, al1, al2, al3, bh2, bh3);
            }
        }
    }

    long r0 = mBase + w * 16 + lq;
#pragma unroll
    for (int t = 0; t < 6; t++) {
        int j = t * 8 + lr * 2;
        storeC(r0,     j,     acc[t][0]);
        storeC(r0,     j + 1, acc[t][1]);
        storeC(r0 + 8, j,     acc[t][2]);
        storeC(r0 + 8, j + 1, acc[t][3]);
    }
}

// ---------------- layer-1 edge aggregation: 4 threads/edge, float4 atomics ----------------
__global__ __launch_bounds__(256) void k_edge1(const int* __restrict__ ei,
                                               const float* __restrict__ pa) {
    int t = blockIdx.x * 256 + threadIdx.x;
    int e = t >> 2;
    if (e >= NE) return;
    int c4 = t & 3;
    int src = clampN(ei[e]);
    int dst = clampN(ei[NE + e]);
    float p = pa[e];
    const float4* yp = (const float4*)(g_Y + src * 32 + 8 * c4);
    float4 ya = yp[0];
    float4 yb = yp[1];
    float4 m;
    m.x = fmaf(p, ya.y - ya.x, ya.x);
    m.y = fmaf(p, ya.w - ya.z, ya.z);
    m.z = fmaf(p, yb.y - yb.x, yb.x);
    m.w = fmaf(p, yb.w - yb.z, yb.z);
    atomicAdd((float4*)(g_S1 + dst * 16 + 4 * c4), m);
    if (c4 == 0) atomicAdd(&g_deg[dst], 1);
}

// ---------------- node update: x1 = elu(S1/deg + R + b1) ----------------
__global__ __launch_bounds__(256) void k_node1(const float* __restrict__ b1,
                                               float* __restrict__ x1out, int writeOut) {
    int t = blockIdx.x * 256 + threadIdx.x;
    int node = t >> 4;
    if (node >= NN) return;
    int c = t & 15;
    int deg = g_deg[node];
    float inv = 1.f / (float)(deg > 0 ? deg : 1);
    float v = fmaf(g_S1[node * 16 + c], inv, g_R[node * 16 + c] + b1[c]);
    v = (v > 0.f) ? v : expm1f(v);
    g_x1[node * 16 + c] = v;
    if (writeOut) x1out[node * 16 + c] = v;
}

// ---------------- layer-2 edge aggregation: 8 threads/edge, 1 float4 atomic each ----------------
// g_AB layout per node: [A_0,B_0, A_1,B_1, ..., A_15,B_15]
__global__ __launch_bounds__(256) void k_edge2(const int* __restrict__ ei,
                                               const float* __restrict__ pa) {
    int t = blockIdx.x * 256 + threadIdx.x;
    int e = t >> 3;
    if (e >= NE) return;
    int c2 = t & 7;                     // 2 channels per thread
    int src = clampN(ei[e]);
    int dst = clampN(ei[NE + e]);
    float p = pa[e];
    float q = 1.f - p;
    float2 xv = *(const float2*)(g_x1 + src * 16 + 2 * c2);
    float4 ab = make_float4(q * xv.x, p * xv.x, q * xv.y, p * xv.y);
    atomicAdd((float4*)(g_AB + dst * 32 + 4 * c2), ab);
}

// ---------------- GEMM2 + log_softmax via mma: [128x48] @ W2T[48x48pad] per CTA ----------------
#define ZST 52   // Z smem row stride (fp32 words)
__global__ __launch_bounds__(256) void k_out_mma(const float* __restrict__ b2,
                                                 float* __restrict__ out) {
    __shared__ __align__(16) float Zs[128 * ZST];
    __shared__ __align__(16) __nv_bfloat16 Whi[48 * 56];
    __shared__ __align__(16) __nv_bfloat16 Wlo[48 * 56];
    __shared__ float b2s[NCLS];
    int tid = threadIdx.x, w = tid >> 5, l = tid & 31;
    int lq = l >> 2, lr = l & 3;
    long mBase = (long)blockIdx.x * 128;

    // ---- fill Z: 2 threads per node ----
    {
        int node2 = tid >> 1, half = tid & 1;
        long gnode = mBase + node2;
        int cn = (gnode < NN) ? (int)gnode : (NN - 1);
        int deg = g_deg[cn];
        float inv = 1.f / (float)(deg > 0 ? deg : 1);
        const float4* abp = (const float4*)(g_AB + cn * 32 + half * 16);
        float* zr = Zs + node2 * ZST;
        int cb = half * 8;
#pragma unroll
        for (int i = 0; i < 4; i++) {
            float4 u = abp[i];
            zr[cb + 2 * i]          = u.x * inv;
            zr[16 + cb + 2 * i]     = u.y * inv;
            zr[cb + 2 * i + 1]      = u.z * inv;
            zr[16 + cb + 2 * i + 1] = u.w * inv;
        }
        const float4* xp = (const float4*)(g_x1 + cn * 16 + half * 8);
        float4 x0 = xp[0], x1v = xp[1];
        zr[32 + cb + 0] = x0.x; zr[32 + cb + 1] = x0.y;
        zr[32 + cb + 2] = x0.z; zr[32 + cb + 3] = x0.w;
        zr[32 + cb + 4] = x1v.x; zr[32 + cb + 5] = x1v.y;
        zr[32 + cb + 6] = x1v.z; zr[32 + cb + 7] = x1v.w;
    }
    for (int i = tid; i < 48 * 56 / 8; i += 256) {
        ((uint4*)Whi)[i] = ((const uint4*)g_W2Thi)[i];
        ((uint4*)Wlo)[i] = ((const uint4*)g_W2Tlo)[i];
    }
    if (tid < NCLS) b2s[tid] = b2[tid];
    __syncthreads();

    uint32_t whi_b = smem_u32(Whi);
    uint32_t wlo_b = smem_u32(Wlo);
    uint32_t aw = (w * 16 + lq) * ZST + 2 * lr;
    int n_off = (l & 7) + ((l & 16) ? 8 : 0);
    int kB_off = (l & 8) ? 8 : 0;
    uint32_t bo0 = ((0 * 16 + n_off) * 56 + kB_off) * 2;
    uint32_t bo1 = ((1 * 16 + n_off) * 56 + kB_off) * 2;
    uint32_t bo2 = ((2 * 16 + n_off) * 56 + kB_off) * 2;

    float acc[6][4];
#pragma unroll
    for (int t = 0; t < 6; t++)
#pragma unroll
        for (int i = 0; i < 4; i++) acc[t][i] = 0.f;

#pragma unroll
    for (int ks = 0; ks < 3; ks++) {
        int kc = ks * 16;
        float2 v0 = *(const float2*)(Zs + aw + kc);
        float2 v1 = *(const float2*)(Zs + aw + 8 * ZST + kc);
        float2 v2 = *(const float2*)(Zs + aw + kc + 8);
        float2 v3 = *(const float2*)(Zs + aw + 8 * ZST + kc + 8);
        uint32_t al0, al1, al2, al3;
        uint32_t ah0 = split_hi(v0.x, v0.y, al0);
        uint32_t ah1 = split_hi(v1.x, v1.y, al1);
        uint32_t ah2 = split_hi(v2.x, v2.y, al2);
        uint32_t ah3 = split_hi(v3.x, v3.y, al3);
        uint32_t ko = ks * 32;
        uint32_t bofs[3] = {bo0, bo1, bo2};
#pragma unroll
        for (int tp = 0; tp < 3; tp++) {
            uint32_t bh0, bh1, bh2, bh3, bl0, bl1, bl2, bl3;
            LDSM_X4(bh0, bh1, bh2, bh3, whi_b + bofs[tp] + ko);
            LDSM_X4(bl0, bl1, bl2, bl3, wlo_b + bofs[tp] + ko);
            MMA_BF16(acc[2 * tp],     ah0, ah1, ah2, ah3, bh0, bh1);
            MMA_BF16(acc[2 * tp],     ah0, ah1, ah2, ah3, bl0, bl1);
            MMA_BF16(acc[2 * tp],     al0, al1, al2, al3, bh0, bh1);
            MMA_BF16(acc[2 * tp + 1], ah0, ah1, ah2, ah3, bh2, bh3);
            MMA_BF16(acc[2 * tp + 1], ah0, ah1, ah2, ah3, bl2, bl3);
            MMA_BF16(acc[2 * tp + 1], al0, al1, al2, al3, bh2, bh3);
        }
    }

#pragma unroll
    for (int t = 0; t < 5; t++) {
        int j = t * 8 + 2 * lr;
        acc[t][0] += b2s[j];     acc[t][1] += b2s[j + 1];
        acc[t][2] += b2s[j];     acc[t][3] += b2s[j + 1];
    }
    float mA = -1e30f, mB = -1e30f;
#pragma unroll
    for (int t = 0; t < 5; t++) {
        mA = fmaxf(mA, fmaxf(acc[t][0], acc[t][1]));
        mB = fmaxf(mB, fmaxf(acc[t][2], acc[t][3]));
    }
    mA = fmaxf(mA, __shfl_xor_sync(0xffffffffu, mA, 1));
    mA = fmaxf(mA, __shfl_xor_sync(0xffffffffu, mA, 2));
    mB = fmaxf(mB, __shfl_xor_sync(0xffffffffu, mB, 1));
    mB = fmaxf(mB, __shfl_xor_sync(0xffffffffu, mB, 2));
    float sA = 0.f, sB = 0.f;
#pragma unroll
    for (int t = 0; t < 5; t++) {
        sA += expf(acc[t][0] - mA) + expf(acc[t][1] - mA);
        sB += expf(acc[t][2] - mB) + expf(acc[t][3] - mB);
    }
    sA += __shfl_xor_sync(0xffffffffu, sA, 1);
    sA += __shfl_xor_sync(0xffffffffu, sA, 2);
    sB += __shfl_xor_sync(0xffffffffu, sB, 1);
    sB += __shfl_xor_sync(0xffffffffu, sB, 2);
    float lA = mA + logf(sA);
    float lB = mB + logf(sB);

    long rA = mBase + w * 16 + lq;
    long rB = rA + 8;
#pragma unroll
    for (int t = 0; t < 5; t++) {
        int j = t * 8 + 2 * lr;
        if (rA < NN) {
            out[rA * NCLS + j]     = acc[t][0] - lA;
            out[rA * NCLS + j + 1] = acc[t][1] - lA;
        }
        if (rB < NN) {
            out[rB * NCLS + j]     = acc[t][2] - lB;
            out[rB * NCLS + j + 1] = acc[t][3] - lB;
        }
    }
}

// ---------------- launch ----------------
extern "C" void kernel_launch(void* const* d_in, const int* in_sizes, int n_in,
                              void* d_out, int out_size) {
    const float* x     = (const float*)d_in[0];
    const int*   ei    = (const int*)d_in[1];     // int32 (jax x64 disabled)
    const float* pa    = (const float*)d_in[2];
    const float* W1    = (const float*)d_in[3];
    const float* root1 = (const float*)d_in[4];
    const float* b1    = (const float*)d_in[5];
    const float* W2    = (const float*)d_in[6];
    const float* root2 = (const float*)d_in[7];
    const float* b2    = (const float*)d_in[8];
    float* out = (float*)d_out;

    int writeOut = (out_size >= NN * (NCLS + HID)) ? 1 : 0;
    float* x1out = out + (long)NN * NCLS;

    cudaFuncSetAttribute(k_gemm1_mma, cudaFuncAttributeMaxDynamicSharedMemorySize, G1_SMEM);

    k_packW<<<(48 * FIN + 255) / 256, 256>>>(W1, root1);
    k_zero<<<(NN * 8 + 255) / 256, 256>>>();
    k_gemm1_mma<<<(NN + 127) / 128, 256, G1_SMEM>>>(x);
    k_edge1<<<(NE * 4) / 256, 256>>>(ei, pa);
    k_node1<<<(NN * 16 + 255) / 256, 256>>>(b1, x1out, writeOut);
    k_edge2<<<(NE * 8) / 256, 256>>>(ei, pa);
    k_pack2<<<(48 * 48 + 255) / 256, 256>>>(W2, root2);
    k_out_mma<<<(NN + 127) / 128, 256>>>(b2, out);
}